// round 5
// baseline (speedup 1.0000x reference)
#include <cuda_runtime.h>
#include <cstdint>

#define NN 100000
#define EMAX 1600000
#define D 64
#define NB ((NN + 511) / 512)   // 196 scan blocks

// Scratch (device globals; no allocation allowed)
__device__ __align__(16) float g_h[(size_t)NN * D];
__device__ int g_cnt[NN];
__device__ int g_fill[NN];
__device__ int g_row[NN + 1];
__device__ int g_bsum[NB];
__device__ int g_boff[NB];
__device__ int g_src[EMAX];
__device__ int g_dst[EMAX];
__device__ int g_eidx[EMAX];
__device__ int g_is64;

// ---------------------------------------------------------------------------
// dtype probe (JAX x64 is usually disabled -> edge_index is int32)
// ---------------------------------------------------------------------------
__global__ void detect_kernel(const int* __restrict__ ei32, int E) {
    __shared__ int sm[256];
    int acc = 0;
    for (int i = threadIdx.x; i < 2048; i += 256) {
        long long w = (long long)i * (2LL * E / 2048) | 1LL;
        acc |= ei32[w];
    }
    sm[threadIdx.x] = acc;
    __syncthreads();
    for (int off = 128; off > 0; off >>= 1) {
        if (threadIdx.x < off) sm[threadIdx.x] |= sm[threadIdx.x + off];
        __syncthreads();
    }
    if (threadIdx.x == 0) g_is64 = (sm[0] == 0) ? 1 : 0;
}

__global__ void zero_kernel() {
    int i = blockIdx.x * blockDim.x + threadIdx.x;
    if (i < NN) { g_cnt[i] = 0; g_fill[i] = 0; }
}

__global__ void prep_kernel(const int* __restrict__ ei32, int E) {
    int t = blockIdx.x * blockDim.x + threadIdx.x;
    if (t >= E) return;
    int s, d;
    if (g_is64) {
        const long long* ei = (const long long*)ei32;
        s = (int)ei[t];
        d = (int)ei[(size_t)E + t];
    } else {
        s = ei32[t];
        d = ei32[(size_t)E + t];
    }
    if ((unsigned)s >= NN) s = 0;
    if ((unsigned)d >= NN) d = 0;
    g_src[t] = s;
    g_dst[t] = d;
    atomicAdd(&g_cnt[d], 1);
}

// ---- 3-pass exclusive scan of g_cnt -> g_row ----
__global__ void scan1_kernel() {
    __shared__ int sm[512];
    int i = blockIdx.x * 512 + threadIdx.x;
    sm[threadIdx.x] = (i < NN) ? g_cnt[i] : 0;
    __syncthreads();
    for (int off = 256; off > 0; off >>= 1) {
        if (threadIdx.x < off) sm[threadIdx.x] += sm[threadIdx.x + off];
        __syncthreads();
    }
    if (threadIdx.x == 0) g_bsum[blockIdx.x] = sm[0];
}

__global__ void scan2_kernel() {
    __shared__ int sm[256];
    int v = (threadIdx.x < NB) ? g_bsum[threadIdx.x] : 0;
    sm[threadIdx.x] = v;
    __syncthreads();
    for (int off = 1; off < 256; off <<= 1) {
        int t = (threadIdx.x >= off) ? sm[threadIdx.x - off] : 0;
        __syncthreads();
        sm[threadIdx.x] += t;
        __syncthreads();
    }
    if (threadIdx.x < NB) g_boff[threadIdx.x] = sm[threadIdx.x] - v;
}

__global__ void scan3_kernel() {
    __shared__ int sm[512];
    int i = blockIdx.x * 512 + threadIdx.x;
    int v = (i < NN) ? g_cnt[i] : 0;
    sm[threadIdx.x] = v;
    __syncthreads();
    for (int off = 1; off < 512; off <<= 1) {
        int t = (threadIdx.x >= off) ? sm[threadIdx.x - off] : 0;
        __syncthreads();
        sm[threadIdx.x] += t;
        __syncthreads();
    }
    int incl = sm[threadIdx.x];
    int boff = g_boff[blockIdx.x];
    if (i < NN) g_row[i] = boff + incl - v;
    if (i == NN - 1) g_row[NN] = boff + incl;
}

__global__ void fill_kernel(int E) {
    int t = blockIdx.x * blockDim.x + threadIdx.x;
    if (t >= E) return;
    int d = g_dst[t];
    int ofs = atomicAdd(&g_fill[d], 1);
    g_eidx[g_row[d] + ofs] = g_src[t];
}

// ---------------------------------------------------------------------------
// tf32 helpers (3xTF32 split for near-fp32 accuracy on tensor cores)
// ---------------------------------------------------------------------------
__device__ __forceinline__ unsigned tf32_rna(float v) {
    unsigned u;
    asm("cvt.rna.tf32.f32 %0, %1;" : "=r"(u) : "f"(v));
    return u;
}

__device__ __forceinline__ void mma_tf32(float c[4],
                                         unsigned a0, unsigned a1,
                                         unsigned a2, unsigned a3,
                                         unsigned b0, unsigned b1) {
    asm volatile(
        "mma.sync.aligned.m16n8k8.row.col.f32.tf32.tf32.f32 "
        "{%0,%1,%2,%3}, {%4,%5,%6,%7}, {%8,%9}, {%0,%1,%2,%3};"
        : "+f"(c[0]), "+f"(c[1]), "+f"(c[2]), "+f"(c[3])
        : "r"(a0), "r"(a1), "r"(a2), "r"(a3), "r"(b0), "r"(b1));
}

// ---------------------------------------------------------------------------
// fused layer: aggregate (CSR gather, mean) into smem, then
// out = relu( agg @ Wl^T + bl + x @ Wr^T ) via 3xTF32 tensor-core MMA.
// Block = 256 threads (8 warps) handles a 64-node x 64-col output tile.
// smem stride 68 makes A/B fragment loads bank-conflict-free.
// ---------------------------------------------------------------------------
__global__ __launch_bounds__(256, 4)
void layer_kernel(const float* __restrict__ xin,
                  const float* __restrict__ Wl,
                  const float* __restrict__ bl,
                  const float* __restrict__ Wr,
                  float* __restrict__ out) {
    __shared__ float As[64][68];   // [node][k]
    __shared__ float Bs[64][68];   // [j][k] = W[j][k] (natural row-major)

    int tid  = threadIdx.x;
    int wid  = tid >> 5;
    int lane = tid & 31;
    int gID  = lane >> 2;   // 0..7
    int ctid = lane & 3;    // 0..3
    int node0 = blockIdx.x * 64;

    int m0     = (wid & 3) * 16;   // warp's M offset (0,16,32,48)
    int n0base = (wid >> 2) * 32;  // warp's N offset (0 or 32)

    float c[4][4];
#pragma unroll
    for (int nt = 0; nt < 4; nt++)
#pragma unroll
        for (int i = 0; i < 4; i++) c[nt][i] = 0.0f;

    const float4* __restrict__ x4 = (const float4*)xin;
    int r    = lane & 15;
    int half = lane >> 4;

#pragma unroll
    for (int phase = 0; phase < 2; phase++) {
        // ---- load weights (raw f32; split to tf32 hi/lo in registers) ----
        const float* __restrict__ W = phase ? Wr : Wl;
        for (int i = tid; i < 64 * 64; i += 256) {
            int j = i >> 6, k = i & 63;
            Bs[j][k] = W[i];
        }

        if (phase == 0) {
            // ---- aggregate: each warp gathers 8 nodes into As ----
            for (int nn = 0; nn < 8; nn++) {
                int n = wid * 8 + nn;
                int node = node0 + n;
                float4 acc = make_float4(0.f, 0.f, 0.f, 0.f);
                int deg = 0;
                if (node < NN) {
                    int rs = g_row[node], re = g_row[node + 1];
                    deg = re - rs;
                    for (int j = rs; j < re; j += 32) {
                        int idx = 0;
                        if (j + lane < re) idx = g_eidx[j + lane];
                        int m = min(32, re - j);
                        if (m == 32) {
#pragma unroll
                            for (int k = 0; k < 32; k += 2) {
                                int s = __shfl_sync(0xffffffffu, idx, k + half);
                                float4 v = x4[(size_t)s * 16 + r];
                                acc.x += v.x; acc.y += v.y;
                                acc.z += v.z; acc.w += v.w;
                            }
                        } else {
                            for (int k = 0; k < m; k += 2) {
                                int which = k + half;
                                int s = __shfl_sync(0xffffffffu, idx, which);
                                if (which < m) {
                                    float4 v = x4[(size_t)s * 16 + r];
                                    acc.x += v.x; acc.y += v.y;
                                    acc.z += v.z; acc.w += v.w;
                                }
                            }
                        }
                    }
                }
                acc.x += __shfl_xor_sync(0xffffffffu, acc.x, 16);
                acc.y += __shfl_xor_sync(0xffffffffu, acc.y, 16);
                acc.z += __shfl_xor_sync(0xffffffffu, acc.z, 16);
                acc.w += __shfl_xor_sync(0xffffffffu, acc.w, 16);
                if (half == 0) {
                    float sc = 1.0f / (float)(deg > 0 ? deg : 1);
                    As[n][(r << 2) + 0] = acc.x * sc;
                    As[n][(r << 2) + 1] = acc.y * sc;
                    As[n][(r << 2) + 2] = acc.z * sc;
                    As[n][(r << 2) + 3] = acc.w * sc;
                }
            }
        } else {
            // ---- As = x rows ----
            for (int i = tid; i < 64 * 16; i += 256) {
                int n = i >> 4, kq = i & 15;
                int node = node0 + n;
                float4 v = make_float4(0.f, 0.f, 0.f, 0.f);
                if (node < NN) v = x4[(size_t)node * 16 + kq];
                As[n][(kq << 2) + 0] = v.x;
                As[n][(kq << 2) + 1] = v.y;
                As[n][(kq << 2) + 2] = v.z;
                As[n][(kq << 2) + 3] = v.w;
            }
        }
        __syncthreads();

        // ---- 3xTF32 MMA over K=64 ----
#pragma unroll
        for (int k0 = 0; k0 < 64; k0 += 8) {
            float af0 = As[m0 + gID][k0 + ctid];
            float af1 = As[m0 + gID + 8][k0 + ctid];
            float af2 = As[m0 + gID][k0 + ctid + 4];
            float af3 = As[m0 + gID + 8][k0 + ctid + 4];
            unsigned ah0 = tf32_rna(af0), ah1 = tf32_rna(af1);
            unsigned ah2 = tf32_rna(af2), ah3 = tf32_rna(af3);
            unsigned al0 = tf32_rna(af0 - __uint_as_float(ah0));
            unsigned al1 = tf32_rna(af1 - __uint_as_float(ah1));
            unsigned al2 = tf32_rna(af2 - __uint_as_float(ah2));
            unsigned al3 = tf32_rna(af3 - __uint_as_float(ah3));
#pragma unroll
            for (int nt = 0; nt < 4; nt++) {
                int n = n0base + nt * 8 + gID;
                float bf0 = Bs[n][k0 + ctid];
                float bf1 = Bs[n][k0 + ctid + 4];
                unsigned bh0 = tf32_rna(bf0), bh1 = tf32_rna(bf1);
                unsigned bl0 = tf32_rna(bf0 - __uint_as_float(bh0));
                unsigned bl1 = tf32_rna(bf1 - __uint_as_float(bh1));
                mma_tf32(c[nt], ah0, ah1, ah2, ah3, bh0, bh1);
                mma_tf32(c[nt], al0, al1, al2, al3, bh0, bh1);
                mma_tf32(c[nt], ah0, ah1, ah2, ah3, bl0, bl1);
            }
        }
        __syncthreads();
    }

    // ---- epilogue: bias + relu into As, then coalesced store ----
#pragma unroll
    for (int nt = 0; nt < 4; nt++) {
        int col = n0base + nt * 8 + ctid * 2;
        float b0 = bl[col], b1 = bl[col + 1];
        As[m0 + gID][col]         = fmaxf(c[nt][0] + b0, 0.0f);
        As[m0 + gID][col + 1]     = fmaxf(c[nt][1] + b1, 0.0f);
        As[m0 + gID + 8][col]     = fmaxf(c[nt][2] + b0, 0.0f);
        As[m0 + gID + 8][col + 1] = fmaxf(c[nt][3] + b1, 0.0f);
    }
    __syncthreads();

    for (int i = tid; i < 64 * 16; i += 256) {
        int n = i >> 4, kq = i & 15;
        int node = node0 + n;
        if (node < NN) {
            float4 o;
            o.x = As[n][(kq << 2) + 0];
            o.y = As[n][(kq << 2) + 1];
            o.z = As[n][(kq << 2) + 2];
            o.w = As[n][(kq << 2) + 3];
            ((float4*)out)[(size_t)node * 16 + kq] = o;
        }
    }
}

// ---------------------------------------------------------------------------
extern "C" void kernel_launch(void* const* d_in, const int* in_sizes, int n_in,
                              void* d_out, int out_size) {
    const float* x   = (const float*)d_in[0];
    const int*   ei  = (const int*)d_in[1];
    const float* W1l = (const float*)d_in[2];
    const float* b1l = (const float*)d_in[3];
    const float* W1r = (const float*)d_in[4];
    const float* W2l = (const float*)d_in[5];
    const float* b2l = (const float*)d_in[6];
    const float* W2r = (const float*)d_in[7];
    int E = in_sizes[1] / 2;
    if (E > EMAX) E = EMAX;

    void* h_p = nullptr;
    cudaGetSymbolAddress(&h_p, g_h);
    float* h = (float*)h_p;

    // CSR build
    detect_kernel<<<1, 256>>>(ei, E);
    zero_kernel<<<(NN + 255) / 256, 256>>>();
    prep_kernel<<<(E + 255) / 256, 256>>>(ei, E);
    scan1_kernel<<<NB, 512>>>();
    scan2_kernel<<<1, 256>>>();
    scan3_kernel<<<NB, 512>>>();
    fill_kernel<<<(E + 255) / 256, 256>>>(E);

    // Layers (fused aggregate + dual-GEMM + bias + relu)
    layer_kernel<<<(NN + 63) / 64, 256>>>(x, W1l, b1l, W1r, h);
    layer_kernel<<<(NN + 63) / 64, 256>>>(h, W2l, b2l, W2r, (float*)d_out);
}

// round 6
// speedup vs baseline: 1.3875x; 1.3875x over previous
#include <cuda_runtime.h>
#include <cstdint>

#define NN 100000
#define EMAX 1600000
#define D 64
#define NB ((NN + 511) / 512)   // 196 scan blocks

// Scratch (device globals; no allocation allowed)
__device__ __align__(16) float g_agg[(size_t)NN * D];
__device__ __align__(16) float g_h[(size_t)NN * D];
__device__ int g_cnt[NN];
__device__ int g_fill[NN];
__device__ int g_row[NN + 1];
__device__ int g_bsum[NB];
__device__ int g_boff[NB];
__device__ int g_eidx[EMAX];
__device__ int g_is64;

// ---------------------------------------------------------------------------
// dtype probe (JAX x64 is usually disabled -> edge_index is int32)
// ---------------------------------------------------------------------------
__global__ void detect_kernel(const int* __restrict__ ei32, int E) {
    __shared__ int sm[256];
    int acc = 0;
    for (int i = threadIdx.x; i < 2048; i += 256) {
        long long w = (long long)i * (2LL * E / 2048) | 1LL;
        acc |= ei32[w];
    }
    sm[threadIdx.x] = acc;
    __syncthreads();
    for (int off = 128; off > 0; off >>= 1) {
        if (threadIdx.x < off) sm[threadIdx.x] |= sm[threadIdx.x + off];
        __syncthreads();
    }
    if (threadIdx.x == 0) g_is64 = (sm[0] == 0) ? 1 : 0;
}

__global__ void zero_kernel() {
    int i = blockIdx.x * blockDim.x + threadIdx.x;
    if (i < NN) { g_cnt[i] = 0; g_fill[i] = 0; }
}

__device__ __forceinline__ void decode_edge(const int* __restrict__ ei32,
                                            int E, int t, int& s, int& d) {
    if (g_is64) {
        const long long* ei = (const long long*)ei32;
        s = (int)ei[t];
        d = (int)ei[(size_t)E + t];
    } else {
        s = ei32[t];
        d = ei32[(size_t)E + t];
    }
    if ((unsigned)s >= NN) s = 0;
    if ((unsigned)d >= NN) d = 0;
}

// count in-degree per dst
__global__ void prep_kernel(const int* __restrict__ ei32, int E) {
    int t = blockIdx.x * blockDim.x + threadIdx.x;
    if (t >= E) return;
    int s, d;
    decode_edge(ei32, E, t, s, d);
    atomicAdd(&g_cnt[d], 1);
}

// ---- 3-pass exclusive scan of g_cnt -> g_row ----
__global__ void scan1_kernel() {
    __shared__ int sm[512];
    int i = blockIdx.x * 512 + threadIdx.x;
    sm[threadIdx.x] = (i < NN) ? g_cnt[i] : 0;
    __syncthreads();
    for (int off = 256; off > 0; off >>= 1) {
        if (threadIdx.x < off) sm[threadIdx.x] += sm[threadIdx.x + off];
        __syncthreads();
    }
    if (threadIdx.x == 0) g_bsum[blockIdx.x] = sm[0];
}

__global__ void scan2_kernel() {
    __shared__ int sm[256];
    int v = (threadIdx.x < NB) ? g_bsum[threadIdx.x] : 0;
    sm[threadIdx.x] = v;
    __syncthreads();
    for (int off = 1; off < 256; off <<= 1) {
        int t = (threadIdx.x >= off) ? sm[threadIdx.x - off] : 0;
        __syncthreads();
        sm[threadIdx.x] += t;
        __syncthreads();
    }
    if (threadIdx.x < NB) g_boff[threadIdx.x] = sm[threadIdx.x] - v;
}

__global__ void scan3_kernel() {
    __shared__ int sm[512];
    int i = blockIdx.x * 512 + threadIdx.x;
    int v = (i < NN) ? g_cnt[i] : 0;
    sm[threadIdx.x] = v;
    __syncthreads();
    for (int off = 1; off < 512; off <<= 1) {
        int t = (threadIdx.x >= off) ? sm[threadIdx.x - off] : 0;
        __syncthreads();
        sm[threadIdx.x] += t;
        __syncthreads();
    }
    int incl = sm[threadIdx.x];
    int boff = g_boff[blockIdx.x];
    if (i < NN) g_row[i] = boff + incl - v;
    if (i == NN - 1) g_row[NN] = boff + incl;
}

// scatter edges into CSR slots (int atomics only; decodes edge_index directly)
__global__ void fill_kernel(const int* __restrict__ ei32, int E) {
    int t = blockIdx.x * blockDim.x + threadIdx.x;
    if (t >= E) return;
    int s, d;
    decode_edge(ei32, E, t, s, d);
    int ofs = atomicAdd(&g_fill[d], 1);
    g_eidx[g_row[d] + ofs] = s;
}

// ---------------------------------------------------------------------------
// aggregate: one warp per node; gather x[src] rows, register-accumulate,
// fused mean. No float atomics anywhere. (Unchanged from the 277us R4.)
// ---------------------------------------------------------------------------
__global__ void aggregate_kernel(const float* __restrict__ xin,
                                 float* __restrict__ aggout) {
    int warp = (blockIdx.x * blockDim.x + threadIdx.x) >> 5;
    if (warp >= NN) return;
    int lane = threadIdx.x & 31;
    int r = lane & 15;
    int half = lane >> 4;

    int rs = g_row[warp], re = g_row[warp + 1];
    const float4* __restrict__ x4 = (const float4*)xin;
    float4 acc = make_float4(0.f, 0.f, 0.f, 0.f);

    for (int j = rs; j < re; j += 32) {
        int idx = 0;
        if (j + lane < re) idx = g_eidx[j + lane];
        int m = min(32, re - j);
        if (m == 32) {
#pragma unroll
            for (int k = 0; k < 32; k += 2) {
                int s = __shfl_sync(0xffffffffu, idx, k + half);
                float4 v = x4[(size_t)s * 16 + r];
                acc.x += v.x; acc.y += v.y; acc.z += v.z; acc.w += v.w;
            }
        } else {
            for (int k = 0; k < m; k += 2) {
                int which = k + half;
                int s = __shfl_sync(0xffffffffu, idx, which);
                if (which < m) {
                    float4 v = x4[(size_t)s * 16 + r];
                    acc.x += v.x; acc.y += v.y; acc.z += v.z; acc.w += v.w;
                }
            }
        }
    }
    acc.x += __shfl_xor_sync(0xffffffffu, acc.x, 16);
    acc.y += __shfl_xor_sync(0xffffffffu, acc.y, 16);
    acc.z += __shfl_xor_sync(0xffffffffu, acc.z, 16);
    acc.w += __shfl_xor_sync(0xffffffffu, acc.w, 16);

    if (half == 0) {
        int deg = re - rs;
        float sc = 1.0f / (float)(deg > 0 ? deg : 1);
        acc.x *= sc; acc.y *= sc; acc.z *= sc; acc.w *= sc;
        ((float4*)aggout)[(size_t)warp * 16 + r] = acc;
    }
}

// ---------------------------------------------------------------------------
// tf32 helpers
// ---------------------------------------------------------------------------
__device__ __forceinline__ unsigned tf32_rna(float v) {
    unsigned u;
    asm("cvt.rna.tf32.f32 %0, %1;" : "=r"(u) : "f"(v));
    return u;
}

__device__ __forceinline__ void mma_tf32(float c[4],
                                         unsigned a0, unsigned a1,
                                         unsigned a2, unsigned a3,
                                         unsigned b0, unsigned b1) {
    asm volatile(
        "mma.sync.aligned.m16n8k8.row.col.f32.tf32.tf32.f32 "
        "{%0,%1,%2,%3}, {%4,%5,%6,%7}, {%8,%9}, {%0,%1,%2,%3};"
        : "+f"(c[0]), "+f"(c[1]), "+f"(c[2]), "+f"(c[3])
        : "r"(a0), "r"(a1), "r"(a2), "r"(a3), "r"(b0), "r"(b1));
}

// ---------------------------------------------------------------------------
// tensor-core node update: out = relu( agg @ Wl^T + bl + x @ Wr^T )
// 3xTF32 split precomputed into smem (Ah/Al/Bh/Bl, stride 68 = conflict-free).
// Block: 256 threads, 64-node x 64-col tile. Dynamic smem 69632B.
// ---------------------------------------------------------------------------
#define SMS 68
__global__ __launch_bounds__(256)
void gemm_tc_kernel(const float* __restrict__ agg,
                    const float* __restrict__ xin,
                    const float* __restrict__ Wl,
                    const float* __restrict__ bl,
                    const float* __restrict__ Wr,
                    float* __restrict__ out) {
    extern __shared__ unsigned smem_u[];
    unsigned (*Ah)[SMS] = (unsigned(*)[SMS])smem_u;
    unsigned (*Al)[SMS] = (unsigned(*)[SMS])(smem_u + 64 * SMS);
    unsigned (*Bh)[SMS] = (unsigned(*)[SMS])(smem_u + 2 * 64 * SMS);
    unsigned (*Bl)[SMS] = (unsigned(*)[SMS])(smem_u + 3 * 64 * SMS);

    int tid  = threadIdx.x;
    int lane = tid & 31;
    int wid  = tid >> 5;
    int gID  = lane >> 2;
    int ctid = lane & 3;
    int node0 = blockIdx.x * 64;

    int m0     = (wid & 3) * 16;
    int n0base = (wid >> 2) * 32;

    float c[4][4];
#pragma unroll
    for (int nt = 0; nt < 4; nt++)
#pragma unroll
        for (int i = 0; i < 4; i++) c[nt][i] = 0.0f;

#pragma unroll
    for (int phase = 0; phase < 2; phase++) {
        const float* __restrict__ A = phase ? xin : agg;
        const float* __restrict__ W = phase ? Wr : Wl;

        // stage B: split W rows into hi/lo
        for (int i = tid; i < 64 * 16; i += 256) {
            int j = i >> 4, kq = i & 15;
            float4 v = ((const float4*)W)[(size_t)j * 16 + kq];
            int k = kq << 2;
            unsigned h0 = tf32_rna(v.x), h1 = tf32_rna(v.y);
            unsigned h2 = tf32_rna(v.z), h3 = tf32_rna(v.w);
            Bh[j][k + 0] = h0; Bh[j][k + 1] = h1;
            Bh[j][k + 2] = h2; Bh[j][k + 3] = h3;
            Bl[j][k + 0] = tf32_rna(v.x - __uint_as_float(h0));
            Bl[j][k + 1] = tf32_rna(v.y - __uint_as_float(h1));
            Bl[j][k + 2] = tf32_rna(v.z - __uint_as_float(h2));
            Bl[j][k + 3] = tf32_rna(v.w - __uint_as_float(h3));
        }
        // stage A: split node rows into hi/lo
        for (int i = tid; i < 64 * 16; i += 256) {
            int n = i >> 4, kq = i & 15;
            int node = node0 + n;
            float4 v = make_float4(0.f, 0.f, 0.f, 0.f);
            if (node < NN) v = ((const float4*)A)[(size_t)node * 16 + kq];
            int k = kq << 2;
            unsigned h0 = tf32_rna(v.x), h1 = tf32_rna(v.y);
            unsigned h2 = tf32_rna(v.z), h3 = tf32_rna(v.w);
            Ah[n][k + 0] = h0; Ah[n][k + 1] = h1;
            Ah[n][k + 2] = h2; Ah[n][k + 3] = h3;
            Al[n][k + 0] = tf32_rna(v.x - __uint_as_float(h0));
            Al[n][k + 1] = tf32_rna(v.y - __uint_as_float(h1));
            Al[n][k + 2] = tf32_rna(v.z - __uint_as_float(h2));
            Al[n][k + 3] = tf32_rna(v.w - __uint_as_float(h3));
        }
        __syncthreads();

#pragma unroll
        for (int k0 = 0; k0 < 64; k0 += 8) {
            unsigned ah0 = Ah[m0 + gID][k0 + ctid];
            unsigned ah1 = Ah[m0 + gID + 8][k0 + ctid];
            unsigned ah2 = Ah[m0 + gID][k0 + ctid + 4];
            unsigned ah3 = Ah[m0 + gID + 8][k0 + ctid + 4];
            unsigned al0 = Al[m0 + gID][k0 + ctid];
            unsigned al1 = Al[m0 + gID + 8][k0 + ctid];
            unsigned al2 = Al[m0 + gID][k0 + ctid + 4];
            unsigned al3 = Al[m0 + gID + 8][k0 + ctid + 4];
#pragma unroll
            for (int nt = 0; nt < 4; nt++) {
                int n = n0base + nt * 8 + gID;
                unsigned bh0 = Bh[n][k0 + ctid];
                unsigned bh1 = Bh[n][k0 + ctid + 4];
                unsigned bl0 = Bl[n][k0 + ctid];
                unsigned bl1 = Bl[n][k0 + ctid + 4];
                mma_tf32(c[nt], ah0, ah1, ah2, ah3, bh0, bh1);
                mma_tf32(c[nt], al0, al1, al2, al3, bh0, bh1);
                mma_tf32(c[nt], ah0, ah1, ah2, ah3, bl0, bl1);
            }
        }
        __syncthreads();
    }

    // epilogue: bias + relu staged through smem (reuse Ah as float buffer)
    float (*S)[SMS] = (float(*)[SMS])Ah;
#pragma unroll
    for (int nt = 0; nt < 4; nt++) {
        int col = n0base + nt * 8 + ctid * 2;
        float b0 = bl[col], b1 = bl[col + 1];
        S[m0 + gID][col]         = fmaxf(c[nt][0] + b0, 0.0f);
        S[m0 + gID][col + 1]     = fmaxf(c[nt][1] + b1, 0.0f);
        S[m0 + gID + 8][col]     = fmaxf(c[nt][2] + b0, 0.0f);
        S[m0 + gID + 8][col + 1] = fmaxf(c[nt][3] + b1, 0.0f);
    }
    __syncthreads();

    for (int i = tid; i < 64 * 16; i += 256) {
        int n = i >> 4, kq = i & 15;
        int node = node0 + n;
        if (node < NN) {
            float4 o;
            o.x = S[n][(kq << 2) + 0];
            o.y = S[n][(kq << 2) + 1];
            o.z = S[n][(kq << 2) + 2];
            o.w = S[n][(kq << 2) + 3];
            ((float4*)out)[(size_t)node * 16 + kq] = o;
        }
    }
}

// ---------------------------------------------------------------------------
extern "C" void kernel_launch(void* const* d_in, const int* in_sizes, int n_in,
                              void* d_out, int out_size) {
    const float* x   = (const float*)d_in[0];
    const int*   ei  = (const int*)d_in[1];
    const float* W1l = (const float*)d_in[2];
    const float* b1l = (const float*)d_in[3];
    const float* W1r = (const float*)d_in[4];
    const float* W2l = (const float*)d_in[5];
    const float* b2l = (const float*)d_in[6];
    const float* W2r = (const float*)d_in[7];
    int E = in_sizes[1] / 2;
    if (E > EMAX) E = EMAX;

    void *agg_p = nullptr, *h_p = nullptr;
    cudaGetSymbolAddress(&agg_p, g_agg);
    cudaGetSymbolAddress(&h_p,   g_h);
    float* agg = (float*)agg_p;
    float* h   = (float*)h_p;

    const int SMEM = 4 * 64 * SMS * 4;   // 69632 bytes
    static int smem_set = 0;
    if (!smem_set) {
        cudaFuncSetAttribute(gemm_tc_kernel,
                             cudaFuncAttributeMaxDynamicSharedMemorySize, SMEM);
        smem_set = 1;
    }

    // CSR build
    detect_kernel<<<1, 256>>>(ei, E);
    zero_kernel<<<(NN + 255) / 256, 256>>>();
    prep_kernel<<<(E + 255) / 256, 256>>>(ei, E);
    scan1_kernel<<<NB, 512>>>();
    scan2_kernel<<<1, 256>>>();
    scan3_kernel<<<NB, 512>>>();
    fill_kernel<<<(E + 255) / 256, 256>>>(ei, E);

    // Layer 1
    aggregate_kernel<<<(NN * 32 + 255) / 256, 256>>>(x, agg);
    gemm_tc_kernel<<<(NN + 63) / 64, 256, SMEM>>>(agg, x, W1l, b1l, W1r, h);

    // Layer 2
    aggregate_kernel<<<(NN * 32 + 255) / 256, 256>>>(h, agg);
    gemm_tc_kernel<<<(NN + 63) / 64, 256, SMEM>>>(agg, h, W2l, b2l, W2r,
                                                  (float*)d_out);
}

// round 8
// speedup vs baseline: 1.4960x; 1.0782x over previous
#include <cuda_runtime.h>
#include <cuda_fp16.h>
#include <cstdint>

#define NN 100000
#define EMAX 1600000
#define D 64
#define NB ((NN + 511) / 512)   // 196 scan blocks

// Scratch (device globals; no allocation allowed)
__device__ __align__(16) float  g_agg[(size_t)NN * D];
__device__ __align__(16) float  g_h[(size_t)NN * D];
__device__ __align__(16) __half g_f16[(size_t)NN * D];  // x16, then h16
__device__ int g_cnt[NN];
__device__ int g_fill[NN];
__device__ int g_row[NN + 1];
__device__ int g_bsum[NB];
__device__ int g_eidx[EMAX];
__device__ int g_is64;

// ---------------------------------------------------------------------------
// fused: zero cnt/fill + dtype probe (last block does the probe)
// ---------------------------------------------------------------------------
__global__ void detzero_kernel(const int* __restrict__ ei32, int E) {
    int i = blockIdx.x * blockDim.x + threadIdx.x;
    if (i < NN) { g_cnt[i] = 0; g_fill[i] = 0; }
    if (blockIdx.x == gridDim.x - 1) {
        __shared__ int sm[256];
        int acc = 0;
        for (int t = threadIdx.x; t < 2048; t += 256) {
            long long w = (long long)t * (2LL * E / 2048) | 1LL;
            acc |= ei32[w];
        }
        sm[threadIdx.x] = acc;
        __syncthreads();
        for (int off = 128; off > 0; off >>= 1) {
            if (threadIdx.x < off) sm[threadIdx.x] |= sm[threadIdx.x + off];
            __syncthreads();
        }
        if (threadIdx.x == 0) g_is64 = (sm[0] == 0) ? 1 : 0;
    }
}

__device__ __forceinline__ void decode_edge(const int* __restrict__ ei32,
                                            int E, int t, int& s, int& d) {
    if (g_is64) {
        const long long* ei = (const long long*)ei32;
        s = (int)ei[t];
        d = (int)ei[(size_t)E + t];
    } else {
        s = ei32[t];
        d = ei32[(size_t)E + t];
    }
    if ((unsigned)s >= NN) s = 0;
    if ((unsigned)d >= NN) d = 0;
}

// count in-degree per dst
__global__ void prep_kernel(const int* __restrict__ ei32, int E) {
    int t = blockIdx.x * blockDim.x + threadIdx.x;
    if (t >= E) return;
    int s, d;
    decode_edge(ei32, E, t, s, d);
    atomicAdd(&g_cnt[d], 1);
}

// ---- scan pass 1: per-block sums ----
__global__ void scan1_kernel() {
    __shared__ int sm[512];
    int i = blockIdx.x * 512 + threadIdx.x;
    sm[threadIdx.x] = (i < NN) ? g_cnt[i] : 0;
    __syncthreads();
    for (int off = 256; off > 0; off >>= 1) {
        if (threadIdx.x < off) sm[threadIdx.x] += sm[threadIdx.x + off];
        __syncthreads();
    }
    if (threadIdx.x == 0) g_bsum[blockIdx.x] = sm[0];
}

// ---- scan pass 2 (fused): each block reduces its bsum prefix, then
// local exclusive scan ----
__global__ void scan23_kernel() {
    __shared__ int sm[512];
    int tid = threadIdx.x;
    int pv = (tid < NB && tid < blockIdx.x) ? g_bsum[tid] : 0;
    sm[tid] = pv;
    __syncthreads();
    for (int off = 256; off > 0; off >>= 1) {
        if (tid < off) sm[tid] += sm[tid + off];
        __syncthreads();
    }
    int boff = sm[0];
    __syncthreads();

    int i = blockIdx.x * 512 + tid;
    int v = (i < NN) ? g_cnt[i] : 0;
    sm[tid] = v;
    __syncthreads();
    for (int off = 1; off < 512; off <<= 1) {
        int t = (tid >= off) ? sm[tid - off] : 0;
        __syncthreads();
        sm[tid] += t;
        __syncthreads();
    }
    int incl = sm[tid];
    if (i < NN) g_row[i] = boff + incl - v;
    if (i == NN - 1) g_row[NN] = boff + incl;
}

// scatter edges into CSR slots
__global__ void fill_kernel(const int* __restrict__ ei32, int E) {
    int t = blockIdx.x * blockDim.x + threadIdx.x;
    if (t >= E) return;
    int s, d;
    decode_edge(ei32, E, t, s, d);
    int ofs = atomicAdd(&g_fill[d], 1);
    g_eidx[g_row[d] + ofs] = s;
}

// fp32 -> fp16 feature conversion (x path)
__global__ void cvt16_kernel(const float* __restrict__ xin) {
    int i = blockIdx.x * blockDim.x + threadIdx.x;
    if (i >= NN * 16) return;
    float4 v = ((const float4*)xin)[i];
    __half2* o = (__half2*)g_f16;
    o[i * 2 + 0] = __floats2half2_rn(v.x, v.y);
    o[i * 2 + 1] = __floats2half2_rn(v.z, v.w);
}

// ---------------------------------------------------------------------------
// aggregate (fp16 gather, fp32 accumulate): one warp per node.
// Row = 64 halfs = 128B = 8 x uint4; 8 lanes per edge, 4 edges per step.
// ---------------------------------------------------------------------------
__global__ void aggregate16_kernel(float* __restrict__ aggout) {
    int warp = (blockIdx.x * blockDim.x + threadIdx.x) >> 5;
    if (warp >= NN) return;
    int lane = threadIdx.x & 31;
    int r = lane & 7;       // 16B slot within the 128B row
    int q = lane >> 3;      // which of 4 edges this lane group handles

    int rs = g_row[warp], re = g_row[warp + 1];
    const uint4* __restrict__ x4 = (const uint4*)g_f16;
    float acc[8];
#pragma unroll
    for (int i = 0; i < 8; i++) acc[i] = 0.0f;

    for (int j = rs; j < re; j += 32) {
        int idx = 0;
        if (j + lane < re) idx = g_eidx[j + lane];
        int m = min(32, re - j);
        if (m == 32) {
#pragma unroll
            for (int k = 0; k < 32; k += 4) {
                int s = __shfl_sync(0xffffffffu, idx, k + q);
                uint4 v = x4[(size_t)s * 8 + r];
                float2 f;
                f = __half22float2(*(__half2*)&v.x); acc[0] += f.x; acc[1] += f.y;
                f = __half22float2(*((__half2*)&v.x + 1)); acc[2] += f.x; acc[3] += f.y;
                f = __half22float2(*(__half2*)&v.z); acc[4] += f.x; acc[5] += f.y;
                f = __half22float2(*((__half2*)&v.z + 1)); acc[6] += f.x; acc[7] += f.y;
            }
        } else {
            for (int k = 0; k < m; k += 4) {
                int which = k + q;
                int s = __shfl_sync(0xffffffffu, idx, which);
                if (which < m) {
                    uint4 v = x4[(size_t)s * 8 + r];
                    float2 f;
                    f = __half22float2(*(__half2*)&v.x); acc[0] += f.x; acc[1] += f.y;
                    f = __half22float2(*((__half2*)&v.x + 1)); acc[2] += f.x; acc[3] += f.y;
                    f = __half22float2(*(__half2*)&v.z); acc[4] += f.x; acc[5] += f.y;
                    f = __half22float2(*((__half2*)&v.z + 1)); acc[6] += f.x; acc[7] += f.y;
                }
            }
        }
    }
    // combine the four quarter partials
#pragma unroll
    for (int i = 0; i < 8; i++) {
        acc[i] += __shfl_xor_sync(0xffffffffu, acc[i], 8);
        acc[i] += __shfl_xor_sync(0xffffffffu, acc[i], 16);
    }

    if (q == 0) {
        int deg = re - rs;
        float sc = 1.0f / (float)(deg > 0 ? deg : 1);
        float4 o0 = make_float4(acc[0] * sc, acc[1] * sc, acc[2] * sc, acc[3] * sc);
        float4 o1 = make_float4(acc[4] * sc, acc[5] * sc, acc[6] * sc, acc[7] * sc);
        ((float4*)aggout)[(size_t)warp * 16 + r * 2 + 0] = o0;
        ((float4*)aggout)[(size_t)warp * 16 + r * 2 + 1] = o1;
    }
}

// ---------------------------------------------------------------------------
// tf32 helpers
// ---------------------------------------------------------------------------
__device__ __forceinline__ unsigned tf32_rna(float v) {
    unsigned u;
    asm("cvt.rna.tf32.f32 %0, %1;" : "=r"(u) : "f"(v));
    return u;
}

__device__ __forceinline__ void mma_tf32(float c[4],
                                         unsigned a0, unsigned a1,
                                         unsigned a2, unsigned a3,
                                         unsigned b0, unsigned b1) {
    asm volatile(
        "mma.sync.aligned.m16n8k8.row.col.f32.tf32.tf32.f32 "
        "{%0,%1,%2,%3}, {%4,%5,%6,%7}, {%8,%9}, {%0,%1,%2,%3};"
        : "+f"(c[0]), "+f"(c[1]), "+f"(c[2]), "+f"(c[3])
        : "r"(a0), "r"(a1), "r"(a2), "r"(a3), "r"(b0), "r"(b1));
}

// ---------------------------------------------------------------------------
// tensor-core node update: out = relu( agg @ Wl^T + bl + x @ Wr^T )
// 3xTF32 split precomputed into smem. If emit16, also writes fp16 mirror
// into g_f16 (consumed by the next layer's gather).
// ---------------------------------------------------------------------------
#define SMS 68
__global__ __launch_bounds__(256)
void gemm_tc_kernel(const float* __restrict__ agg,
                    const float* __restrict__ xin,
                    const float* __restrict__ Wl,
                    const float* __restrict__ bl,
                    const float* __restrict__ Wr,
                    float* __restrict__ out, int emit16) {
    extern __shared__ unsigned smem_u[];
    unsigned (*Ah)[SMS] = (unsigned(*)[SMS])smem_u;
    unsigned (*Al)[SMS] = (unsigned(*)[SMS])(smem_u + 64 * SMS);
    unsigned (*Bh)[SMS] = (unsigned(*)[SMS])(smem_u + 2 * 64 * SMS);
    unsigned (*Bl)[SMS] = (unsigned(*)[SMS])(smem_u + 3 * 64 * SMS);

    int tid  = threadIdx.x;
    int lane = tid & 31;
    int wid  = tid >> 5;
    int gID  = lane >> 2;
    int ctid = lane & 3;
    int node0 = blockIdx.x * 64;

    int m0     = (wid & 3) * 16;
    int n0base = (wid >> 2) * 32;

    float c[4][4];
#pragma unroll
    for (int nt = 0; nt < 4; nt++)
#pragma unroll
        for (int i = 0; i < 4; i++) c[nt][i] = 0.0f;

#pragma unroll
    for (int phase = 0; phase < 2; phase++) {
        const float* __restrict__ A = phase ? xin : agg;
        const float* __restrict__ W = phase ? Wr : Wl;

        for (int i = tid; i < 64 * 16; i += 256) {
            int j = i >> 4, kq = i & 15;
            float4 v = ((const float4*)W)[(size_t)j * 16 + kq];
            int k = kq << 2;
            unsigned h0 = tf32_rna(v.x), h1 = tf32_rna(v.y);
            unsigned h2 = tf32_rna(v.z), h3 = tf32_rna(v.w);
            Bh[j][k + 0] = h0; Bh[j][k + 1] = h1;
            Bh[j][k + 2] = h2; Bh[j][k + 3] = h3;
            Bl[j][k + 0] = tf32_rna(v.x - __uint_as_float(h0));
            Bl[j][k + 1] = tf32_rna(v.y - __uint_as_float(h1));
            Bl[j][k + 2] = tf32_rna(v.z - __uint_as_float(h2));
            Bl[j][k + 3] = tf32_rna(v.w - __uint_as_float(h3));
        }
        for (int i = tid; i < 64 * 16; i += 256) {
            int n = i >> 4, kq = i & 15;
            int node = node0 + n;
            float4 v = make_float4(0.f, 0.f, 0.f, 0.f);
            if (node < NN) v = ((const float4*)A)[(size_t)node * 16 + kq];
            int k = kq << 2;
            unsigned h0 = tf32_rna(v.x), h1 = tf32_rna(v.y);
            unsigned h2 = tf32_rna(v.z), h3 = tf32_rna(v.w);
            Ah[n][k + 0] = h0; Ah[n][k + 1] = h1;
            Ah[n][k + 2] = h2; Ah[n][k + 3] = h3;
            Al[n][k + 0] = tf32_rna(v.x - __uint_as_float(h0));
            Al[n][k + 1] = tf32_rna(v.y - __uint_as_float(h1));
            Al[n][k + 2] = tf32_rna(v.z - __uint_as_float(h2));
            Al[n][k + 3] = tf32_rna(v.w - __uint_as_float(h3));
        }
        __syncthreads();

#pragma unroll
        for (int k0 = 0; k0 < 64; k0 += 8) {
            unsigned ah0 = Ah[m0 + gID][k0 + ctid];
            unsigned ah1 = Ah[m0 + gID + 8][k0 + ctid];
            unsigned ah2 = Ah[m0 + gID][k0 + ctid + 4];
            unsigned ah3 = Ah[m0 + gID + 8][k0 + ctid + 4];
            unsigned al0 = Al[m0 + gID][k0 + ctid];
            unsigned al1 = Al[m0 + gID + 8][k0 + ctid];
            unsigned al2 = Al[m0 + gID][k0 + ctid + 4];
            unsigned al3 = Al[m0 + gID + 8][k0 + ctid + 4];
#pragma unroll
            for (int nt = 0; nt < 4; nt++) {
                int n = n0base + nt * 8 + gID;
                unsigned bh0 = Bh[n][k0 + ctid];
                unsigned bh1 = Bh[n][k0 + ctid + 4];
                unsigned bl0 = Bl[n][k0 + ctid];
                unsigned bl1 = Bl[n][k0 + ctid + 4];
                mma_tf32(c[nt], ah0, ah1, ah2, ah3, bh0, bh1);
                mma_tf32(c[nt], al0, al1, al2, al3, bh0, bh1);
                mma_tf32(c[nt], ah0, ah1, ah2, ah3, bl0, bl1);
            }
        }
        __syncthreads();
    }

    // epilogue: bias + relu staged through smem
    float (*S)[SMS] = (float(*)[SMS])Ah;
#pragma unroll
    for (int nt = 0; nt < 4; nt++) {
        int col = n0base + nt * 8 + ctid * 2;
        float b0 = bl[col], b1 = bl[col + 1];
        S[m0 + gID][col]         = fmaxf(c[nt][0] + b0, 0.0f);
        S[m0 + gID][col + 1]     = fmaxf(c[nt][1] + b1, 0.0f);
        S[m0 + gID + 8][col]     = fmaxf(c[nt][2] + b0, 0.0f);
        S[m0 + gID + 8][col + 1] = fmaxf(c[nt][3] + b1, 0.0f);
    }
    __syncthreads();

    for (int i = tid; i < 64 * 16; i += 256) {
        int n = i >> 4, kq = i & 15;
        int node = node0 + n;
        if (node < NN) {
            float4 o;
            o.x = S[n][(kq << 2) + 0];
            o.y = S[n][(kq << 2) + 1];
            o.z = S[n][(kq << 2) + 2];
            o.w = S[n][(kq << 2) + 3];
            ((float4*)out)[(size_t)node * 16 + kq] = o;
            if (emit16) {
                __half2* o16 = (__half2*)g_f16;
                o16[(size_t)node * 32 + kq * 2 + 0] = __floats2half2_rn(o.x, o.y);
                o16[(size_t)node * 32 + kq * 2 + 1] = __floats2half2_rn(o.z, o.w);
            }
        }
    }
}

// ---------------------------------------------------------------------------
extern "C" void kernel_launch(void* const* d_in, const int* in_sizes, int n_in,
                              void* d_out, int out_size) {
    const float* x   = (const float*)d_in[0];
    const int*   ei  = (const int*)d_in[1];
    const float* W1l = (const float*)d_in[2];
    const float* b1l = (const float*)d_in[3];
    const float* W1r = (const float*)d_in[4];
    const float* W2l = (const float*)d_in[5];
    const float* b2l = (const float*)d_in[6];
    const float* W2r = (const float*)d_in[7];
    int E = in_sizes[1] / 2;
    if (E > EMAX) E = EMAX;

    void *agg_p = nullptr, *h_p = nullptr;
    cudaGetSymbolAddress(&agg_p, g_agg);
    cudaGetSymbolAddress(&h_p,   g_h);
    float* agg = (float*)agg_p;
    float* h   = (float*)h_p;

    const int SMEM = 4 * 64 * SMS * 4;   // 69632 bytes
    static int smem_set = 0;
    if (!smem_set) {
        cudaFuncSetAttribute(gemm_tc_kernel,
                             cudaFuncAttributeMaxDynamicSharedMemorySize, SMEM);
        smem_set = 1;
    }

    // CSR build + x16 conversion
    detzero_kernel<<<(NN + 255) / 256, 256>>>(ei, E);
    prep_kernel<<<(E + 255) / 256, 256>>>(ei, E);
    scan1_kernel<<<NB, 512>>>();
    scan23_kernel<<<NB, 512>>>();
    fill_kernel<<<(E + 255) / 256, 256>>>(ei, E);
    cvt16_kernel<<<(NN * 16 + 255) / 256, 256>>>(x);

    // Layer 1 (gemm emits h + h16)
    aggregate16_kernel<<<(NN * 32 + 255) / 256, 256>>>(agg);
    gemm_tc_kernel<<<(NN + 63) / 64, 256, SMEM>>>(agg, x, W1l, b1l, W1r, h, 1);

    // Layer 2
    aggregate16_kernel<<<(NN * 32 + 255) / 256, 256>>>(agg);
    gemm_tc_kernel<<<(NN + 63) / 64, 256, SMEM>>>(agg, h, W2l, b2l, W2r,
                                                  (float*)d_out, 0);
}

// round 9
// speedup vs baseline: 1.7442x; 1.1659x over previous
#include <cuda_runtime.h>
#include <cuda_fp16.h>
#include <cstdint>

#define NN 100000
#define EMAX 1600000
#define D 64
#define NB ((NN + 511) / 512)   // 196 scan blocks

// Scratch (device globals; no allocation allowed)
__device__ __align__(16) float  g_agg[(size_t)NN * D];
__device__ __align__(16) float  g_h[(size_t)NN * D];
__device__ __align__(16) __half g_f16[(size_t)NN * D];  // x16, then h16
__device__ int g_cnt[NN];
__device__ int g_fill[NN];
__device__ int g_row[NN + 1];
__device__ int g_bsum[NB];
__device__ int g_eidx[EMAX];
__device__ int g_is64;

// ---------------------------------------------------------------------------
// fused: zero cnt/fill + fp32->fp16 x conversion + dtype probe (last block)
// grid covers NN*16 float4 elements
// ---------------------------------------------------------------------------
__global__ void detcvt_kernel(const int* __restrict__ ei32, int E,
                              const float* __restrict__ xin) {
    int i = blockIdx.x * blockDim.x + threadIdx.x;
    if (i < NN * 16) {
        float4 v = ((const float4*)xin)[i];
        __half2* o = (__half2*)g_f16;
        o[i * 2 + 0] = __floats2half2_rn(v.x, v.y);
        o[i * 2 + 1] = __floats2half2_rn(v.z, v.w);
    }
    if (i < NN) { g_cnt[i] = 0; g_fill[i] = 0; }
    if (blockIdx.x == gridDim.x - 1) {
        __shared__ int sm[256];
        int acc = 0;
        for (int t = threadIdx.x; t < 2048; t += 256) {
            long long w = (long long)t * (2LL * E / 2048) | 1LL;
            acc |= ei32[w];
        }
        sm[threadIdx.x] = acc;
        __syncthreads();
        for (int off = 128; off > 0; off >>= 1) {
            if (threadIdx.x < off) sm[threadIdx.x] |= sm[threadIdx.x + off];
            __syncthreads();
        }
        if (threadIdx.x == 0) g_is64 = (sm[0] == 0) ? 1 : 0;
    }
}

__device__ __forceinline__ void decode_edge(const int* __restrict__ ei32,
                                            int E, int t, int& s, int& d) {
    if (g_is64) {
        const long long* ei = (const long long*)ei32;
        s = (int)ei[t];
        d = (int)ei[(size_t)E + t];
    } else {
        s = ei32[t];
        d = ei32[(size_t)E + t];
    }
    if ((unsigned)s >= NN) s = 0;
    if ((unsigned)d >= NN) d = 0;
}

// count in-degree per dst (dst column only)
__global__ void prep_kernel(const int* __restrict__ ei32, int E) {
    int t = blockIdx.x * blockDim.x + threadIdx.x;
    if (t >= E) return;
    int d;
    if (g_is64) d = (int)((const long long*)ei32)[(size_t)E + t];
    else        d = ei32[(size_t)E + t];
    if ((unsigned)d >= NN) d = 0;
    atomicAdd(&g_cnt[d], 1);
}

// ---- scan pass 1: per-block sums ----
__global__ void scan1_kernel() {
    __shared__ int sm[512];
    int i = blockIdx.x * 512 + threadIdx.x;
    sm[threadIdx.x] = (i < NN) ? g_cnt[i] : 0;
    __syncthreads();
    for (int off = 256; off > 0; off >>= 1) {
        if (threadIdx.x < off) sm[threadIdx.x] += sm[threadIdx.x + off];
        __syncthreads();
    }
    if (threadIdx.x == 0) g_bsum[blockIdx.x] = sm[0];
}

// ---- scan pass 2: each block reduces its bsum prefix, then local scan ----
__global__ void scan23_kernel() {
    __shared__ int sm[512];
    int tid = threadIdx.x;
    int pv = (tid < NB && tid < blockIdx.x) ? g_bsum[tid] : 0;
    sm[tid] = pv;
    __syncthreads();
    for (int off = 256; off > 0; off >>= 1) {
        if (tid < off) sm[tid] += sm[tid + off];
        __syncthreads();
    }
    int boff = sm[0];
    __syncthreads();

    int i = blockIdx.x * 512 + tid;
    int v = (i < NN) ? g_cnt[i] : 0;
    sm[tid] = v;
    __syncthreads();
    for (int off = 1; off < 512; off <<= 1) {
        int t = (tid >= off) ? sm[tid - off] : 0;
        __syncthreads();
        sm[tid] += t;
        __syncthreads();
    }
    int incl = sm[tid];
    if (i < NN) g_row[i] = boff + incl - v;
    if (i == NN - 1) g_row[NN] = boff + incl;
}

// scatter edges into CSR slots
__global__ void fill_kernel(const int* __restrict__ ei32, int E) {
    int t = blockIdx.x * blockDim.x + threadIdx.x;
    if (t >= E) return;
    int s, d;
    decode_edge(ei32, E, t, s, d);
    int ofs = atomicAdd(&g_fill[d], 1);
    g_eidx[g_row[d] + ofs] = s;
}

// ---------------------------------------------------------------------------
// aggregate (fp16 gather, fp32 accumulate): one warp per node.
// ---------------------------------------------------------------------------
__global__ void aggregate16_kernel(float* __restrict__ aggout) {
    int warp = (blockIdx.x * blockDim.x + threadIdx.x) >> 5;
    if (warp >= NN) return;
    int lane = threadIdx.x & 31;
    int r = lane & 7;       // 16B slot within the 128B row
    int q = lane >> 3;      // which of 4 edges this lane group handles

    int rs = g_row[warp], re = g_row[warp + 1];
    const uint4* __restrict__ x4 = (const uint4*)g_f16;
    float acc[8];
#pragma unroll
    for (int i = 0; i < 8; i++) acc[i] = 0.0f;

    for (int j = rs; j < re; j += 32) {
        int idx = 0;
        if (j + lane < re) idx = g_eidx[j + lane];
        int m = min(32, re - j);
        if (m == 32) {
#pragma unroll
            for (int k = 0; k < 32; k += 4) {
                int s = __shfl_sync(0xffffffffu, idx, k + q);
                uint4 v = x4[(size_t)s * 8 + r];
                float2 f;
                f = __half22float2(*(__half2*)&v.x); acc[0] += f.x; acc[1] += f.y;
                f = __half22float2(*((__half2*)&v.x + 1)); acc[2] += f.x; acc[3] += f.y;
                f = __half22float2(*(__half2*)&v.z); acc[4] += f.x; acc[5] += f.y;
                f = __half22float2(*((__half2*)&v.z + 1)); acc[6] += f.x; acc[7] += f.y;
            }
        } else {
            for (int k = 0; k < m; k += 4) {
                int which = k + q;
                int s = __shfl_sync(0xffffffffu, idx, which);
                if (which < m) {
                    uint4 v = x4[(size_t)s * 8 + r];
                    float2 f;
                    f = __half22float2(*(__half2*)&v.x); acc[0] += f.x; acc[1] += f.y;
                    f = __half22float2(*((__half2*)&v.x + 1)); acc[2] += f.x; acc[3] += f.y;
                    f = __half22float2(*(__half2*)&v.z); acc[4] += f.x; acc[5] += f.y;
                    f = __half22float2(*((__half2*)&v.z + 1)); acc[6] += f.x; acc[7] += f.y;
                }
            }
        }
    }
#pragma unroll
    for (int i = 0; i < 8; i++) {
        acc[i] += __shfl_xor_sync(0xffffffffu, acc[i], 8);
        acc[i] += __shfl_xor_sync(0xffffffffu, acc[i], 16);
    }

    if (q == 0) {
        int deg = re - rs;
        float sc = 1.0f / (float)(deg > 0 ? deg : 1);
        float4 o0 = make_float4(acc[0] * sc, acc[1] * sc, acc[2] * sc, acc[3] * sc);
        float4 o1 = make_float4(acc[4] * sc, acc[5] * sc, acc[6] * sc, acc[7] * sc);
        ((float4*)aggout)[(size_t)warp * 16 + r * 2 + 0] = o0;
        ((float4*)aggout)[(size_t)warp * 16 + r * 2 + 1] = o1;
    }
}

// ---------------------------------------------------------------------------
// fp16 MMA helper (m16n8k16, fp32 accum)
// ---------------------------------------------------------------------------
__device__ __forceinline__ void mma_f16(float c[4],
                                        unsigned a0, unsigned a1,
                                        unsigned a2, unsigned a3,
                                        unsigned b0, unsigned b1) {
    asm volatile(
        "mma.sync.aligned.m16n8k16.row.col.f32.f16.f16.f32 "
        "{%0,%1,%2,%3}, {%4,%5,%6,%7}, {%8,%9}, {%0,%1,%2,%3};"
        : "+f"(c[0]), "+f"(c[1]), "+f"(c[2]), "+f"(c[3])
        : "r"(a0), "r"(a1), "r"(a2), "r"(a3), "r"(b0), "r"(b1));
}

// pack two floats into hi-half2 and lo-half2 (split residual)
__device__ __forceinline__ void split2(float x, float y,
                                       unsigned& hi, unsigned& lo) {
    __half hx = __float2half_rn(x), hy = __float2half_rn(y);
    __half lx = __float2half_rn(x - __half2float(hx));
    __half ly = __float2half_rn(y - __half2float(hy));
    __half2 h = __halves2half2(hx, hy), l = __halves2half2(lx, ly);
    hi = *(unsigned*)&h;
    lo = *(unsigned*)&l;
}

// ---------------------------------------------------------------------------
// split-fp16 tensor-core node update:
// out = relu( agg @ Wl^T + bl + x @ Wr^T )
// A,W split into hi+lo fp16; D += Ah*Bh + Al*Bh + Ah*Bl (fp32 accum).
// Static smem 36.9KB, stride-36 half2 rows (conflict-free).
// ---------------------------------------------------------------------------
#define K2P 36   // half2 stride per row
__global__ __launch_bounds__(256)
void gemm_f16_kernel(const float* __restrict__ agg,
                     const float* __restrict__ xin,
                     const float* __restrict__ Wl,
                     const float* __restrict__ bl,
                     const float* __restrict__ Wr,
                     float* __restrict__ out, int emit16) {
    __shared__ __align__(16) unsigned Ah2[64][K2P];
    __shared__ __align__(16) unsigned Al2[64][K2P];
    __shared__ __align__(16) unsigned Bh2[64][K2P];
    __shared__ __align__(16) unsigned Bl2[64][K2P];

    int tid  = threadIdx.x;
    int lane = tid & 31;
    int wid  = tid >> 5;
    int gID  = lane >> 2;
    int ctid = lane & 3;
    int node0 = blockIdx.x * 64;

    int m0     = (wid & 3) * 16;
    int n0base = (wid >> 2) * 32;

    float c[4][4];
#pragma unroll
    for (int nt = 0; nt < 4; nt++)
#pragma unroll
        for (int i = 0; i < 4; i++) c[nt][i] = 0.0f;

#pragma unroll
    for (int phase = 0; phase < 2; phase++) {
        const float* __restrict__ A = phase ? xin : agg;
        const float* __restrict__ W = phase ? Wr : Wl;

        // stage B (weights): hi/lo half2
        for (int i = tid; i < 64 * 16; i += 256) {
            int j = i >> 4, kq = i & 15;
            float4 v = ((const float4*)W)[(size_t)j * 16 + kq];
            unsigned h0, l0, h1, l1;
            split2(v.x, v.y, h0, l0);
            split2(v.z, v.w, h1, l1);
            Bh2[j][kq * 2 + 0] = h0; Bh2[j][kq * 2 + 1] = h1;
            Bl2[j][kq * 2 + 0] = l0; Bl2[j][kq * 2 + 1] = l1;
        }
        // stage A (node rows): hi/lo half2
        for (int i = tid; i < 64 * 16; i += 256) {
            int n = i >> 4, kq = i & 15;
            int node = node0 + n;
            float4 v = make_float4(0.f, 0.f, 0.f, 0.f);
            if (node < NN) v = ((const float4*)A)[(size_t)node * 16 + kq];
            unsigned h0, l0, h1, l1;
            split2(v.x, v.y, h0, l0);
            split2(v.z, v.w, h1, l1);
            Ah2[n][kq * 2 + 0] = h0; Ah2[n][kq * 2 + 1] = h1;
            Al2[n][kq * 2 + 0] = l0; Al2[n][kq * 2 + 1] = l1;
        }
        __syncthreads();

        // K=64 in 4 steps of 16 (8 half2 per step)
#pragma unroll
        for (int k0h = 0; k0h < 32; k0h += 8) {
            unsigned ah0 = Ah2[m0 + gID][k0h + ctid];
            unsigned ah1 = Ah2[m0 + gID + 8][k0h + ctid];
            unsigned ah2 = Ah2[m0 + gID][k0h + 4 + ctid];
            unsigned ah3 = Ah2[m0 + gID + 8][k0h + 4 + ctid];
            unsigned al0 = Al2[m0 + gID][k0h + ctid];
            unsigned al1 = Al2[m0 + gID + 8][k0h + ctid];
            unsigned al2 = Al2[m0 + gID][k0h + 4 + ctid];
            unsigned al3 = Al2[m0 + gID + 8][k0h + 4 + ctid];
#pragma unroll
            for (int nt = 0; nt < 4; nt++) {
                int n = n0base + nt * 8 + gID;
                unsigned bh0 = Bh2[n][k0h + ctid];
                unsigned bh1 = Bh2[n][k0h + 4 + ctid];
                unsigned bl0 = Bl2[n][k0h + ctid];
                unsigned bl1 = Bl2[n][k0h + 4 + ctid];
                mma_f16(c[nt], ah0, ah1, ah2, ah3, bh0, bh1);
                mma_f16(c[nt], al0, al1, al2, al3, bh0, bh1);
                mma_f16(c[nt], ah0, ah1, ah2, ah3, bl0, bl1);
            }
        }
        __syncthreads();
    }

    // epilogue: bias + relu staged through smem (reuse Ah2/Al2 region)
    float (*S)[68] = (float(*)[68])&Ah2[0][0];   // 64*68*4 = 17408B < 2*9216B*... fits
#pragma unroll
    for (int nt = 0; nt < 4; nt++) {
        int col = n0base + nt * 8 + ctid * 2;
        float b0 = bl[col], b1 = bl[col + 1];
        S[m0 + gID][col]         = fmaxf(c[nt][0] + b0, 0.0f);
        S[m0 + gID][col + 1]     = fmaxf(c[nt][1] + b1, 0.0f);
        S[m0 + gID + 8][col]     = fmaxf(c[nt][2] + b0, 0.0f);
        S[m0 + gID + 8][col + 1] = fmaxf(c[nt][3] + b1, 0.0f);
    }
    __syncthreads();

    for (int i = tid; i < 64 * 16; i += 256) {
        int n = i >> 4, kq = i & 15;
        int node = node0 + n;
        if (node < NN) {
            float4 o;
            o.x = S[n][(kq << 2) + 0];
            o.y = S[n][(kq << 2) + 1];
            o.z = S[n][(kq << 2) + 2];
            o.w = S[n][(kq << 2) + 3];
            ((float4*)out)[(size_t)node * 16 + kq] = o;
            if (emit16) {
                __half2* o16 = (__half2*)g_f16;
                o16[(size_t)node * 32 + kq * 2 + 0] = __floats2half2_rn(o.x, o.y);
                o16[(size_t)node * 32 + kq * 2 + 1] = __floats2half2_rn(o.z, o.w);
            }
        }
    }
}

// ---------------------------------------------------------------------------
extern "C" void kernel_launch(void* const* d_in, const int* in_sizes, int n_in,
                              void* d_out, int out_size) {
    const float* x   = (const float*)d_in[0];
    const int*   ei  = (const int*)d_in[1];
    const float* W1l = (const float*)d_in[2];
    const float* b1l = (const float*)d_in[3];
    const float* W1r = (const float*)d_in[4];
    const float* W2l = (const float*)d_in[5];
    const float* b2l = (const float*)d_in[6];
    const float* W2r = (const float*)d_in[7];
    int E = in_sizes[1] / 2;
    if (E > EMAX) E = EMAX;

    void *agg_p = nullptr, *h_p = nullptr;
    cudaGetSymbolAddress(&agg_p, g_agg);
    cudaGetSymbolAddress(&h_p,   g_h);
    float* agg = (float*)agg_p;
    float* h   = (float*)h_p;

    // CSR build + x16 conversion (fused)
    detcvt_kernel<<<(NN * 16 + 255) / 256, 256>>>(ei, E, x);
    prep_kernel<<<(E + 255) / 256, 256>>>(ei, E);
    scan1_kernel<<<NB, 512>>>();
    scan23_kernel<<<NB, 512>>>();
    fill_kernel<<<(E + 255) / 256, 256>>>(ei, E);

    // Layer 1 (gemm emits h + h16)
    aggregate16_kernel<<<(NN * 32 + 255) / 256, 256>>>(agg);
    gemm_f16_kernel<<<(NN + 63) / 64, 256>>>(agg, x, W1l, b1l, W1r, h, 1);

    // Layer 2
    aggregate16_kernel<<<(NN * 32 + 255) / 256, 256>>>(agg);
    gemm_f16_kernel<<<(NN + 63) / 64, 256>>>(agg, h, W2l, b2l, W2r,
                                             (float*)d_out, 0);
}

// round 10
// speedup vs baseline: 1.9943x; 1.1434x over previous
#include <cuda_runtime.h>
#include <cuda_fp16.h>
#include <cstdint>

#define NN 100000
#define EMAX 1600000
#define D 64
#define NB ((NN + 511) / 512)   // 196 scan blocks

// Scratch (device globals; no allocation allowed)
__device__ __align__(16) __half g_x16[(size_t)NN * D];
__device__ __align__(16) __half g_h16[(size_t)NN * D];
__device__ __align__(16) __half g_agg16[(size_t)NN * D];
__device__ int g_cnt[NN];
__device__ int g_fill[NN];
__device__ int g_row[NN + 1];
__device__ int g_bsum[NB];
__device__ int g_eidx[EMAX];
__device__ int g_is64;

// ---------------------------------------------------------------------------
// fused: zero cnt/fill + fp32->fp16 x conversion + dtype probe (last block)
// ---------------------------------------------------------------------------
__global__ void detcvt_kernel(const int* __restrict__ ei32, int E,
                              const float* __restrict__ xin) {
    int i = blockIdx.x * blockDim.x + threadIdx.x;
    if (i < NN * 16) {
        float4 v = ((const float4*)xin)[i];
        __half2* o = (__half2*)g_x16;
        o[i * 2 + 0] = __floats2half2_rn(v.x, v.y);
        o[i * 2 + 1] = __floats2half2_rn(v.z, v.w);
    }
    if (i < NN) { g_cnt[i] = 0; g_fill[i] = 0; }
    if (blockIdx.x == gridDim.x - 1) {
        __shared__ int sm[256];
        int acc = 0;
        for (int t = threadIdx.x; t < 2048; t += 256) {
            long long w = (long long)t * (2LL * E / 2048) | 1LL;
            acc |= ei32[w];
        }
        sm[threadIdx.x] = acc;
        __syncthreads();
        for (int off = 128; off > 0; off >>= 1) {
            if (threadIdx.x < off) sm[threadIdx.x] |= sm[threadIdx.x + off];
            __syncthreads();
        }
        if (threadIdx.x == 0) g_is64 = (sm[0] == 0) ? 1 : 0;
    }
}

__device__ __forceinline__ void decode_edge(const int* __restrict__ ei32,
                                            int E, int t, int& s, int& d) {
    if (g_is64) {
        const long long* ei = (const long long*)ei32;
        s = (int)ei[t];
        d = (int)ei[(size_t)E + t];
    } else {
        s = ei32[t];
        d = ei32[(size_t)E + t];
    }
    if ((unsigned)s >= NN) s = 0;
    if ((unsigned)d >= NN) d = 0;
}

// count in-degree per dst (dst column only)
__global__ void prep_kernel(const int* __restrict__ ei32, int E) {
    int t = blockIdx.x * blockDim.x + threadIdx.x;
    if (t >= E) return;
    int d;
    if (g_is64) d = (int)((const long long*)ei32)[(size_t)E + t];
    else        d = ei32[(size_t)E + t];
    if ((unsigned)d >= NN) d = 0;
    atomicAdd(&g_cnt[d], 1);
}

// ---- scan pass 1: per-block sums ----
__global__ void scan1_kernel() {
    __shared__ int sm[512];
    int i = blockIdx.x * 512 + threadIdx.x;
    sm[threadIdx.x] = (i < NN) ? g_cnt[i] : 0;
    __syncthreads();
    for (int off = 256; off > 0; off >>= 1) {
        if (threadIdx.x < off) sm[threadIdx.x] += sm[threadIdx.x + off];
        __syncthreads();
    }
    if (threadIdx.x == 0) g_bsum[blockIdx.x] = sm[0];
}

// ---- scan pass 2: each block reduces its bsum prefix, then local scan ----
__global__ void scan23_kernel() {
    __shared__ int sm[512];
    int tid = threadIdx.x;
    int pv = (tid < NB && tid < blockIdx.x) ? g_bsum[tid] : 0;
    sm[tid] = pv;
    __syncthreads();
    for (int off = 256; off > 0; off >>= 1) {
        if (tid < off) sm[tid] += sm[tid + off];
        __syncthreads();
    }
    int boff = sm[0];
    __syncthreads();

    int i = blockIdx.x * 512 + tid;
    int v = (i < NN) ? g_cnt[i] : 0;
    sm[tid] = v;
    __syncthreads();
    for (int off = 1; off < 512; off <<= 1) {
        int t = (tid >= off) ? sm[tid - off] : 0;
        __syncthreads();
        sm[tid] += t;
        __syncthreads();
    }
    int incl = sm[tid];
    if (i < NN) g_row[i] = boff + incl - v;
    if (i == NN - 1) g_row[NN] = boff + incl;
}

// scatter edges into CSR slots
__global__ void fill_kernel(const int* __restrict__ ei32, int E) {
    int t = blockIdx.x * blockDim.x + threadIdx.x;
    if (t >= E) return;
    int s, d;
    decode_edge(ei32, E, t, s, d);
    int ofs = atomicAdd(&g_fill[d], 1);
    g_eidx[g_row[d] + ofs] = s;
}

// ---------------------------------------------------------------------------
// aggregate: fp16 gather, fp32 accumulate, fp16 mean output. Warp per node.
// ---------------------------------------------------------------------------
__global__ void aggregate16_kernel(const __half* __restrict__ src,
                                   __half* __restrict__ dst) {
    int warp = (blockIdx.x * blockDim.x + threadIdx.x) >> 5;
    if (warp >= NN) return;
    int lane = threadIdx.x & 31;
    int r = lane & 7;       // 16B slot within the 128B row
    int q = lane >> 3;      // which of 4 edges this lane group handles

    int rs = g_row[warp], re = g_row[warp + 1];
    const uint4* __restrict__ x4 = (const uint4*)src;
    float acc[8];
#pragma unroll
    for (int i = 0; i < 8; i++) acc[i] = 0.0f;

    for (int j = rs; j < re; j += 32) {
        int idx = 0;
        if (j + lane < re) idx = g_eidx[j + lane];
        int m = min(32, re - j);
        if (m == 32) {
#pragma unroll
            for (int k = 0; k < 32; k += 4) {
                int s = __shfl_sync(0xffffffffu, idx, k + q);
                uint4 v = x4[(size_t)s * 8 + r];
                float2 f;
                f = __half22float2(*(__half2*)&v.x); acc[0] += f.x; acc[1] += f.y;
                f = __half22float2(*((__half2*)&v.x + 1)); acc[2] += f.x; acc[3] += f.y;
                f = __half22float2(*(__half2*)&v.z); acc[4] += f.x; acc[5] += f.y;
                f = __half22float2(*((__half2*)&v.z + 1)); acc[6] += f.x; acc[7] += f.y;
            }
        } else {
            for (int k = 0; k < m; k += 4) {
                int which = k + q;
                int s = __shfl_sync(0xffffffffu, idx, which);
                if (which < m) {
                    uint4 v = x4[(size_t)s * 8 + r];
                    float2 f;
                    f = __half22float2(*(__half2*)&v.x); acc[0] += f.x; acc[1] += f.y;
                    f = __half22float2(*((__half2*)&v.x + 1)); acc[2] += f.x; acc[3] += f.y;
                    f = __half22float2(*(__half2*)&v.z); acc[4] += f.x; acc[5] += f.y;
                    f = __half22float2(*((__half2*)&v.z + 1)); acc[6] += f.x; acc[7] += f.y;
                }
            }
        }
    }
#pragma unroll
    for (int i = 0; i < 8; i++) {
        acc[i] += __shfl_xor_sync(0xffffffffu, acc[i], 8);
        acc[i] += __shfl_xor_sync(0xffffffffu, acc[i], 16);
    }

    if (q == 0) {
        int deg = re - rs;
        float sc = 1.0f / (float)(deg > 0 ? deg : 1);
        __half2 o[4];
        o[0] = __floats2half2_rn(acc[0] * sc, acc[1] * sc);
        o[1] = __floats2half2_rn(acc[2] * sc, acc[3] * sc);
        o[2] = __floats2half2_rn(acc[4] * sc, acc[5] * sc);
        o[3] = __floats2half2_rn(acc[6] * sc, acc[7] * sc);
        ((uint4*)dst)[(size_t)warp * 8 + r] = *(uint4*)o;
    }
}

// ---------------------------------------------------------------------------
// fp16 MMA helper (m16n8k16, fp32 accum)
// ---------------------------------------------------------------------------
__device__ __forceinline__ void mma_f16(float c[4],
                                        unsigned a0, unsigned a1,
                                        unsigned a2, unsigned a3,
                                        unsigned b0, unsigned b1) {
    asm volatile(
        "mma.sync.aligned.m16n8k16.row.col.f32.f16.f16.f32 "
        "{%0,%1,%2,%3}, {%4,%5,%6,%7}, {%8,%9}, {%0,%1,%2,%3};"
        : "+f"(c[0]), "+f"(c[1]), "+f"(c[2]), "+f"(c[3])
        : "r"(a0), "r"(a1), "r"(a2), "r"(a3), "r"(b0), "r"(b1));
}

__device__ __forceinline__ void split2(float x, float y,
                                       unsigned& hi, unsigned& lo) {
    __half hx = __float2half_rn(x), hy = __float2half_rn(y);
    __half lx = __float2half_rn(x - __half2float(hx));
    __half ly = __float2half_rn(y - __half2float(hy));
    __half2 h = __halves2half2(hx, hy), l = __halves2half2(lx, ly);
    hi = *(unsigned*)&h;
    lo = *(unsigned*)&l;
}

// ---------------------------------------------------------------------------
// fp16-A tensor-core node update:
// out = relu( A0 @ Wl^T + bl + A1 @ Wr^T ),  A0/A1 already fp16.
// Weights split hi/lo (exact); per k-step: A*Bh + A*Bl (fp32 accum).
// Writes fp32 out (if outf) and/or fp16 mirror (if out16).
// ---------------------------------------------------------------------------
#define K2P 36   // half2 stride per row (u32 units)
__global__ __launch_bounds__(256)
void gemm_f16_kernel(const __half* __restrict__ A0,
                     const __half* __restrict__ A1,
                     const float* __restrict__ Wl,
                     const float* __restrict__ bl,
                     const float* __restrict__ Wr,
                     float* outf, __half* out16) {
    // single carved buffer so the epilogue reuse is well-defined
    __shared__ __align__(16) unsigned smem_all[3 * 64 * K2P];
    unsigned (*Ah2)[K2P] = (unsigned(*)[K2P])smem_all;
    unsigned (*Bh2)[K2P] = (unsigned(*)[K2P])(smem_all + 64 * K2P);
    unsigned (*Bl2)[K2P] = (unsigned(*)[K2P])(smem_all + 2 * 64 * K2P);

    int tid  = threadIdx.x;
    int lane = tid & 31;
    int wid  = tid >> 5;
    int gID  = lane >> 2;
    int ctid = lane & 3;
    int node0 = blockIdx.x * 64;

    int m0     = (wid & 3) * 16;
    int n0base = (wid >> 2) * 32;

    float c[4][4];
#pragma unroll
    for (int nt = 0; nt < 4; nt++)
#pragma unroll
        for (int i = 0; i < 4; i++) c[nt][i] = 0.0f;

#pragma unroll
    for (int phase = 0; phase < 2; phase++) {
        const __half* __restrict__ A = phase ? A1 : A0;
        const float*  __restrict__ W = phase ? Wr : Wl;

        // stage B (fp32 weights -> hi/lo half2)
        for (int i = tid; i < 64 * 16; i += 256) {
            int j = i >> 4, kq = i & 15;
            float4 v = ((const float4*)W)[(size_t)j * 16 + kq];
            unsigned h0, l0, h1, l1;
            split2(v.x, v.y, h0, l0);
            split2(v.z, v.w, h1, l1);
            Bh2[j][kq * 2 + 0] = h0; Bh2[j][kq * 2 + 1] = h1;
            Bl2[j][kq * 2 + 0] = l0; Bl2[j][kq * 2 + 1] = l1;
        }
        // stage A (already fp16): copy uint4 (4 half2) chunks
        for (int i = tid; i < 64 * 8; i += 256) {
            int n = i >> 3, c4 = i & 7;
            int node = node0 + n;
            uint4 v = make_uint4(0u, 0u, 0u, 0u);
            if (node < NN) v = ((const uint4*)A)[(size_t)node * 8 + c4];
            Ah2[n][c4 * 4 + 0] = v.x;
            Ah2[n][c4 * 4 + 1] = v.y;
            Ah2[n][c4 * 4 + 2] = v.z;
            Ah2[n][c4 * 4 + 3] = v.w;
        }
        __syncthreads();

        // K=64 in 4 steps of 16 halves (8 half2 per step)
#pragma unroll
        for (int k0h = 0; k0h < 32; k0h += 8) {
            unsigned a0 = Ah2[m0 + gID][k0h + ctid];
            unsigned a1 = Ah2[m0 + gID + 8][k0h + ctid];
            unsigned a2 = Ah2[m0 + gID][k0h + 4 + ctid];
            unsigned a3 = Ah2[m0 + gID + 8][k0h + 4 + ctid];
#pragma unroll
            for (int nt = 0; nt < 4; nt++) {
                int n = n0base + nt * 8 + gID;
                unsigned bh0 = Bh2[n][k0h + ctid];
                unsigned bh1 = Bh2[n][k0h + 4 + ctid];
                unsigned bl0 = Bl2[n][k0h + ctid];
                unsigned bl1 = Bl2[n][k0h + 4 + ctid];
                mma_f16(c[nt], a0, a1, a2, a3, bh0, bh1);
                mma_f16(c[nt], a0, a1, a2, a3, bl0, bl1);
            }
        }
        __syncthreads();
    }

    // epilogue: bias + relu staged through smem (64 x 68 floats = 17408B,
    // fits inside the 27648B carved buffer; B tiles dead by now)
    float (*S)[68] = (float(*)[68])smem_all;
#pragma unroll
    for (int nt = 0; nt < 4; nt++) {
        int col = n0base + nt * 8 + ctid * 2;
        float b0 = bl[col], b1 = bl[col + 1];
        S[m0 + gID][col]         = fmaxf(c[nt][0] + b0, 0.0f);
        S[m0 + gID][col + 1]     = fmaxf(c[nt][1] + b1, 0.0f);
        S[m0 + gID + 8][col]     = fmaxf(c[nt][2] + b0, 0.0f);
        S[m0 + gID + 8][col + 1] = fmaxf(c[nt][3] + b1, 0.0f);
    }
    __syncthreads();

    for (int i = tid; i < 64 * 16; i += 256) {
        int n = i >> 4, kq = i & 15;
        int node = node0 + n;
        if (node < NN) {
            float4 o;
            o.x = S[n][(kq << 2) + 0];
            o.y = S[n][(kq << 2) + 1];
            o.z = S[n][(kq << 2) + 2];
            o.w = S[n][(kq << 2) + 3];
            if (outf)
                ((float4*)outf)[(size_t)node * 16 + kq] = o;
            if (out16) {
                __half2* o16 = (__half2*)out16;
                o16[(size_t)node * 32 + kq * 2 + 0] = __floats2half2_rn(o.x, o.y);
                o16[(size_t)node * 32 + kq * 2 + 1] = __floats2half2_rn(o.z, o.w);
            }
        }
    }
}

// ---------------------------------------------------------------------------
extern "C" void kernel_launch(void* const* d_in, const int* in_sizes, int n_in,
                              void* d_out, int out_size) {
    const float* x   = (const float*)d_in[0];
    const int*   ei  = (const int*)d_in[1];
    const float* W1l = (const float*)d_in[2];
    const float* b1l = (const float*)d_in[3];
    const float* W1r = (const float*)d_in[4];
    const float* W2l = (const float*)d_in[5];
    const float* b2l = (const float*)d_in[6];
    const float* W2r = (const float*)d_in[7];
    int E = in_sizes[1] / 2;
    if (E > EMAX) E = EMAX;

    void *x16_p = nullptr, *h16_p = nullptr, *agg16_p = nullptr;
    cudaGetSymbolAddress(&x16_p,   g_x16);
    cudaGetSymbolAddress(&h16_p,   g_h16);
    cudaGetSymbolAddress(&agg16_p, g_agg16);
    __half* x16   = (__half*)x16_p;
    __half* h16   = (__half*)h16_p;
    __half* agg16 = (__half*)agg16_p;

    // CSR build + x16 conversion (fused)
    detcvt_kernel<<<(NN * 16 + 255) / 256, 256>>>(ei, E, x);
    prep_kernel<<<(E + 255) / 256, 256>>>(ei, E);
    scan1_kernel<<<NB, 512>>>();
    scan23_kernel<<<NB, 512>>>();
    fill_kernel<<<(E + 255) / 256, 256>>>(ei, E);

    // Layer 1: h16 only (no fp32 h)
    aggregate16_kernel<<<(NN * 32 + 255) / 256, 256>>>(x16, agg16);
    gemm_f16_kernel<<<(NN + 63) / 64, 256>>>(agg16, x16, W1l, b1l, W1r,
                                             nullptr, h16);

    // Layer 2: fp32 out
    aggregate16_kernel<<<(NN * 32 + 255) / 256, 256>>>(h16, agg16);
    gemm_f16_kernel<<<(NN + 63) / 64, 256>>>(agg16, h16, W2l, b2l, W2r,
                                             (float*)d_out, nullptr);
}